// round 1
// baseline (speedup 1.0000x reference)
#include <cuda_runtime.h>
#include <cuda_bf16.h>
#include <cstdint>

#define N_NODES 50000
#define N_EDGES 1600000
#define IN_F    256
#define OUT_F   128
#define N_REL   500

// ---------------- scratch (device globals; no allocations allowed) ----------
__device__ float g_Wh[(size_t)N_NODES * OUT_F];   // 25.6 MB
__device__ float g_si[N_NODES];
__device__ float g_sj[N_NODES];
__device__ float g_srel[N_REL];
__device__ int   g_cnt[N_NODES];
__device__ int   g_off[N_NODES + 1];
__device__ int   g_cur[N_NODES];
__device__ float g_cw[N_EDGES];                   // per-edge exp weight (CSR order)
__device__ int   g_cc[N_EDGES];                   // per-edge col       (CSR order)

// ---------------- zero counters ---------------------------------------------
__global__ void zero_cnt_kernel() {
    int i = blockIdx.x * blockDim.x + threadIdx.x;
    if (i < N_NODES) g_cnt[i] = 0;
}

// ---------------- SGEMM: Wh = h @ W  (M x 256 @ 256 x 128) ------------------
// BM=128, BN=128, BK=16, 256 threads, 8x8 per-thread tile.
__global__ __launch_bounds__(256) void gemm_kernel(const float* __restrict__ A,
                                                   const float* __restrict__ B,
                                                   int M) {
    __shared__ float As[16][128 + 4];
    __shared__ float Bs[16][128];
    int t = threadIdx.x;
    int block_m = blockIdx.x * 128;
    int tx = t & 15;       // 0..15 -> 8 output cols each
    int ty = t >> 4;       // 0..15 -> 8 output rows each

    float acc[8][8];
#pragma unroll
    for (int i = 0; i < 8; i++)
#pragma unroll
        for (int j = 0; j < 8; j++) acc[i][j] = 0.f;

    for (int k0 = 0; k0 < IN_F; k0 += 16) {
        // load A tile 128x16 (transposed into As[k][m])
#pragma unroll
        for (int s = 0; s < 2; s++) {
            int i = t + s * 256;            // float4 index, 512 total
            int row = i >> 2;               // 0..127
            int c4 = i & 3;                 // 0..3
            int grow = block_m + row;
            if (grow >= M) grow = M - 1;    // clamp (stores guarded)
            float4 v = *(const float4*)(A + (size_t)grow * IN_F + k0 + c4 * 4);
            As[c4 * 4 + 0][row] = v.x;
            As[c4 * 4 + 1][row] = v.y;
            As[c4 * 4 + 2][row] = v.z;
            As[c4 * 4 + 3][row] = v.w;
        }
        // load B tile 16x128
#pragma unroll
        for (int s = 0; s < 2; s++) {
            int i = t + s * 256;            // float4 index, 512 total
            int row = i >> 5;               // 0..15
            int c4 = i & 31;                // 0..31
            float4 v = *(const float4*)(B + (size_t)(k0 + row) * OUT_F + c4 * 4);
            *(float4*)&Bs[row][c4 * 4] = v;
        }
        __syncthreads();
#pragma unroll
        for (int k = 0; k < 16; k++) {
            float ra[8], rb[8];
#pragma unroll
            for (int i = 0; i < 8; i++) ra[i] = As[k][ty * 8 + i];
#pragma unroll
            for (int i = 0; i < 8; i++) rb[i] = Bs[k][tx * 8 + i];
#pragma unroll
            for (int i = 0; i < 8; i++)
#pragma unroll
                for (int j = 0; j < 8; j++) acc[i][j] += ra[i] * rb[j];
        }
        __syncthreads();
    }
#pragma unroll
    for (int i = 0; i < 8; i++) {
        int grow = block_m + ty * 8 + i;
        if (grow < M) {
#pragma unroll
            for (int j = 0; j < 8; j += 4) {
                float4 v = make_float4(acc[i][j], acc[i][j + 1], acc[i][j + 2], acc[i][j + 3]);
                *(float4*)(g_Wh + (size_t)grow * OUT_F + tx * 8 + j) = v;
            }
        }
    }
}

// ---------------- per-node / per-rel attention dot products ------------------
// warp per node: s_i = Wh[n].a[0:128], s_j = Wh[n].a[128:256]
// warps [N_NODES, N_NODES+N_REL): s_rel = rel_emb[r].a[256:384]
__global__ void dots_kernel(const float* __restrict__ a,
                            const float* __restrict__ rel_emb) {
    int gw = (blockIdx.x * blockDim.x + threadIdx.x) >> 5;
    int lane = threadIdx.x & 31;
    if (gw < N_NODES) {
        float4 v = ((const float4*)g_Wh)[(size_t)gw * 32 + lane];
        float4 ai = ((const float4*)a)[lane];
        float4 aj = ((const float4*)(a + 128))[lane];
        float si = v.x * ai.x + v.y * ai.y + v.z * ai.z + v.w * ai.w;
        float sj = v.x * aj.x + v.y * aj.y + v.z * aj.z + v.w * aj.w;
#pragma unroll
        for (int o = 16; o; o >>= 1) {
            si += __shfl_xor_sync(0xffffffffu, si, o);
            sj += __shfl_xor_sync(0xffffffffu, sj, o);
        }
        if (lane == 0) { g_si[gw] = si; g_sj[gw] = sj; }
    } else if (gw < N_NODES + N_REL) {
        int r = gw - N_NODES;
        float4 v = ((const float4*)rel_emb)[(size_t)r * 32 + lane];
        float4 ar = ((const float4*)(a + 256))[lane];
        float s = v.x * ar.x + v.y * ar.y + v.z * ar.z + v.w * ar.w;
#pragma unroll
        for (int o = 16; o; o >>= 1) s += __shfl_xor_sync(0xffffffffu, s, o);
        if (lane == 0) g_srel[r] = s;
    }
}

// ---------------- CSR build --------------------------------------------------
__global__ void count_kernel(const int* __restrict__ rows) {
    int e = blockIdx.x * blockDim.x + threadIdx.x;
    if (e < N_EDGES) atomicAdd(&g_cnt[rows[e]], 1);
}

// single-block exclusive scan of 50000 counts
__global__ void scan_kernel() {
    __shared__ int part[1024];
    const int C = (N_NODES + 1023) / 1024;  // 49
    int t = threadIdx.x;
    int base = t * C;
    int s = 0;
    for (int i = 0; i < C; i++) {
        int idx = base + i;
        if (idx < N_NODES) s += g_cnt[idx];
    }
    part[t] = s;
    __syncthreads();
    // Hillis-Steele inclusive scan
    for (int d = 1; d < 1024; d <<= 1) {
        int v = (t >= d) ? part[t - d] : 0;
        __syncthreads();
        part[t] += v;
        __syncthreads();
    }
    int run = part[t] - s;  // exclusive prefix of this chunk
    for (int i = 0; i < C; i++) {
        int idx = base + i;
        if (idx < N_NODES) {
            g_off[idx] = run;
            g_cur[idx] = run;
            run += g_cnt[idx];
        }
    }
    if (t == 1023) g_off[N_NODES] = part[1023];
}

// per-edge: compute exp(leaky(e)) (global max skipped: shift-invariant up to eps,
// effect <= 1e-9 rel) and scatter (w, col) into CSR slots.
__global__ void scatter_kernel(const int* __restrict__ rows,
                               const int* __restrict__ cols,
                               const int* __restrict__ et) {
    int e = blockIdx.x * blockDim.x + threadIdx.x;
    if (e >= N_EDGES) return;
    int r = rows[e], c = cols[e], tt = et[e];
    float x = g_si[r] + g_sj[c] + g_srel[tt];
    x = x > 0.f ? x : 0.2f * x;       // leaky_relu
    float w = expf(x);
    int p = atomicAdd(&g_cur[r], 1);
    g_cw[p] = w;
    g_cc[p] = c;
}

// ---------------- aggregation: one warp per node, no output atomics ---------
__global__ void agg_kernel(float* __restrict__ out) {
    int warp = (blockIdx.x * blockDim.x + threadIdx.x) >> 5;
    int lane = threadIdx.x & 31;
    if (warp >= N_NODES) return;
    int beg = g_off[warp];
    int end = g_off[warp + 1];

    float4 acc = make_float4(0.f, 0.f, 0.f, 0.f);
    float sumw = 0.f;
    const float4* Wh4 = (const float4*)g_Wh;

    for (int k = beg; k < end; k += 32) {
        int idx = k + lane;
        float w = 0.f;
        int c = 0;
        if (idx < end) { w = g_cw[idx]; c = g_cc[idx]; }
        int m = end - k;
        if (m > 32) m = 32;
#pragma unroll 4
        for (int j = 0; j < m; j++) {
            float wj = __shfl_sync(0xffffffffu, w, j);
            int cj = __shfl_sync(0xffffffffu, c, j);
            float4 v = Wh4[(size_t)cj * 32 + lane];
            acc.x += wj * v.x;
            acc.y += wj * v.y;
            acc.z += wj * v.z;
            acc.w += wj * v.w;
            sumw += wj;
        }
    }
    float inv = 1.f / (sumw + 1e-10f);
    float4 o;
    o.x = acc.x * inv; o.y = acc.y * inv; o.z = acc.z * inv; o.w = acc.w * inv;
    // elu
    o.x = o.x > 0.f ? o.x : expf(o.x) - 1.f;
    o.y = o.y > 0.f ? o.y : expf(o.y) - 1.f;
    o.z = o.z > 0.f ? o.z : expf(o.z) - 1.f;
    o.w = o.w > 0.f ? o.w : expf(o.w) - 1.f;
    ((float4*)out)[(size_t)warp * 32 + lane] = o;
}

// ---------------- launch -----------------------------------------------------
extern "C" void kernel_launch(void* const* d_in, const int* in_sizes, int n_in,
                              void* d_out, int out_size) {
    const float* h    = (const float*)d_in[0];
    const int*   rows = (const int*)d_in[1];
    const int*   cols = (const int*)d_in[2];
    const int*   et   = (const int*)d_in[3];
    const float* W    = (const float*)d_in[4];
    const float* rel  = (const float*)d_in[5];
    const float* a    = (const float*)d_in[6];
    float* out = (float*)d_out;

    zero_cnt_kernel<<<(N_NODES + 255) / 256, 256>>>();

    gemm_kernel<<<(N_NODES + 127) / 128, 256>>>(h, W, N_NODES);

    int dot_warps = N_NODES + N_REL;
    dots_kernel<<<(dot_warps * 32 + 255) / 256, 256>>>(a, rel);

    count_kernel<<<(N_EDGES + 255) / 256, 256>>>(rows);
    scan_kernel<<<1, 1024>>>();
    scatter_kernel<<<(N_EDGES + 255) / 256, 256>>>(rows, cols, et);

    agg_kernel<<<(N_NODES * 32 + 255) / 256, 256>>>(out);
}

// round 2
// speedup vs baseline: 1.0974x; 1.0974x over previous
#include <cuda_runtime.h>
#include <cuda_fp16.h>
#include <cstdint>

#define N_NODES 50000
#define N_EDGES 1600000
#define IN_F    256
#define OUT_F   128
#define N_REL   500

// ---------------- scratch (device globals; no allocations allowed) ----------
__device__ __half g_Whh[(size_t)N_NODES * OUT_F]; // 12.8 MB fp16 gather table
__device__ float  g_si[N_NODES];
__device__ float  g_sj[N_NODES];
__device__ float  g_srel[N_REL];
__device__ int    g_cnt[N_NODES];
__device__ int    g_off[N_NODES + 1];
__device__ int    g_cur[N_NODES];
__device__ uint2  g_wc[N_EDGES];                  // {w bits, col} in CSR order

// ---------------- zero counters ---------------------------------------------
__global__ void zero_cnt_kernel() {
    int i = blockIdx.x * blockDim.x + threadIdx.x;
    if (i < N_NODES) g_cnt[i] = 0;
}

// ---------------- SGEMM + fused epilogue -------------------------------------
// Wh = h @ W (fp32 math). Epilogue: write fp16 Wh, compute si = Wh.a_i,
// sj = Wh.a_j per row (block owns the full 128-col row). fp32 Wh never stored.
__global__ __launch_bounds__(256) void gemm_kernel(const float* __restrict__ A,
                                                   const float* __restrict__ B,
                                                   const float* __restrict__ a,
                                                   int M) {
    __shared__ float As[16][132];   // 132*4B = 16B-aligned rows
    __shared__ float Bs[16][128];
    int t = threadIdx.x;
    int block_m = blockIdx.x * 128;
    int tx = t & 15;       // 16 col-groups of 8
    int ty = t >> 4;       // 16 row-groups of 8

    float acc[8][8];
#pragma unroll
    for (int i = 0; i < 8; i++)
#pragma unroll
        for (int j = 0; j < 8; j++) acc[i][j] = 0.f;

    for (int k0 = 0; k0 < IN_F; k0 += 16) {
#pragma unroll
        for (int s = 0; s < 2; s++) {
            int i = t + s * 256;            // float4 index, 512 total
            int row = i >> 2;               // 0..127
            int c4 = i & 3;                 // 0..3
            int grow = block_m + row;
            if (grow >= M) grow = M - 1;    // clamp (stores guarded)
            float4 v = *(const float4*)(A + (size_t)grow * IN_F + k0 + c4 * 4);
            As[c4 * 4 + 0][row] = v.x;
            As[c4 * 4 + 1][row] = v.y;
            As[c4 * 4 + 2][row] = v.z;
            As[c4 * 4 + 3][row] = v.w;
        }
#pragma unroll
        for (int s = 0; s < 2; s++) {
            int i = t + s * 256;
            int row = i >> 5;               // 0..15
            int c4 = i & 31;                // 0..31
            float4 v = *(const float4*)(B + (size_t)(k0 + row) * OUT_F + c4 * 4);
            *(float4*)&Bs[row][c4 * 4] = v;
        }
        __syncthreads();
#pragma unroll
        for (int k = 0; k < 16; k++) {
            float ra[8], rb[8];
#pragma unroll
            for (int i = 0; i < 8; i++) ra[i] = As[k][ty * 8 + i];
#pragma unroll
            for (int i = 0; i < 8; i++) rb[i] = Bs[k][tx * 8 + i];
#pragma unroll
            for (int i = 0; i < 8; i++)
#pragma unroll
                for (int j = 0; j < 8; j++) acc[i][j] += ra[i] * rb[j];
        }
        __syncthreads();
    }

    // epilogue: fp16 store + fused attention dots
    float ai_r[8], aj_r[8];
#pragma unroll
    for (int j = 0; j < 8; j++) {
        ai_r[j] = a[tx * 8 + j];
        aj_r[j] = a[128 + tx * 8 + j];
    }
#pragma unroll
    for (int i = 0; i < 8; i++) {
        int grow = block_m + ty * 8 + i;
        bool valid = grow < M;
        if (valid) {
            __half hb[8];
#pragma unroll
            for (int j = 0; j < 8; j++) hb[j] = __float2half_rn(acc[i][j]);
            *(uint4*)(g_Whh + (size_t)grow * OUT_F + tx * 8) = *(uint4*)hb;
        }
        float si = 0.f, sj = 0.f;
#pragma unroll
        for (int j = 0; j < 8; j++) {
            si += acc[i][j] * ai_r[j];
            sj += acc[i][j] * aj_r[j];
        }
        // reduce across the 16 tx lanes (contiguous within half-warp)
#pragma unroll
        for (int o = 8; o; o >>= 1) {
            si += __shfl_xor_sync(0xffffffffu, si, o);
            sj += __shfl_xor_sync(0xffffffffu, sj, o);
        }
        if (tx == 0 && valid) { g_si[grow] = si; g_sj[grow] = sj; }
    }
}

// ---------------- rel_emb dot products (tiny: 500 warps) ---------------------
__global__ void rel_dots_kernel(const float* __restrict__ a,
                                const float* __restrict__ rel_emb) {
    int gw = (blockIdx.x * blockDim.x + threadIdx.x) >> 5;
    int lane = threadIdx.x & 31;
    if (gw >= N_REL) return;
    float4 v = ((const float4*)rel_emb)[(size_t)gw * 32 + lane];
    float4 ar = ((const float4*)(a + 256))[lane];
    float s = v.x * ar.x + v.y * ar.y + v.z * ar.z + v.w * ar.w;
#pragma unroll
    for (int o = 16; o; o >>= 1) s += __shfl_xor_sync(0xffffffffu, s, o);
    if (lane == 0) g_srel[gw] = s;
}

// ---------------- CSR build --------------------------------------------------
__global__ void count_kernel(const int* __restrict__ rows) {
    int e = blockIdx.x * blockDim.x + threadIdx.x;
    if (e < N_EDGES) atomicAdd(&g_cnt[rows[e]], 1);
}

__global__ void scan_kernel() {
    __shared__ int part[1024];
    const int C = (N_NODES + 1023) / 1024;  // 49
    int t = threadIdx.x;
    int base = t * C;
    int s = 0;
    for (int i = 0; i < C; i++) {
        int idx = base + i;
        if (idx < N_NODES) s += g_cnt[idx];
    }
    part[t] = s;
    __syncthreads();
    for (int d = 1; d < 1024; d <<= 1) {
        int v = (t >= d) ? part[t - d] : 0;
        __syncthreads();
        part[t] += v;
        __syncthreads();
    }
    int run = part[t] - s;
    for (int i = 0; i < C; i++) {
        int idx = base + i;
        if (idx < N_NODES) {
            g_off[idx] = run;
            g_cur[idx] = run;
            run += g_cnt[idx];
        }
    }
    if (t == 1023) g_off[N_NODES] = part[1023];
}

// per-edge exp weight (global max skipped: softmax shift-invariant up to eps,
// effect <= 1e-9 rel) scattered with its col into CSR slots as one uint2.
__global__ void scatter_kernel(const int* __restrict__ rows,
                               const int* __restrict__ cols,
                               const int* __restrict__ et) {
    int e = blockIdx.x * blockDim.x + threadIdx.x;
    if (e >= N_EDGES) return;
    int r = rows[e], c = cols[e], tt = et[e];
    float x = g_si[r] + g_sj[c] + g_srel[tt];
    x = x > 0.f ? x : 0.2f * x;       // leaky_relu
    float w = expf(x);
    int p = atomicAdd(&g_cur[r], 1);
    g_wc[p] = make_uint2(__float_as_uint(w), (unsigned)c);
}

// ---------------- aggregation: one warp per node, fp16 gathers ---------------
__global__ void agg_kernel(float* __restrict__ out) {
    int warp = (blockIdx.x * blockDim.x + threadIdx.x) >> 5;
    int lane = threadIdx.x & 31;
    if (warp >= N_NODES) return;
    int beg = g_off[warp];
    int end = g_off[warp + 1];

    float4 acc = make_float4(0.f, 0.f, 0.f, 0.f);
    float sumw = 0.f;

    for (int k = beg; k < end; k += 32) {
        int idx = k + lane;
        uint2 wc = make_uint2(0u, 0u);
        if (idx < end) wc = g_wc[idx];
        int m = end - k;
        if (m > 32) m = 32;
#pragma unroll 4
        for (int j = 0; j < m; j++) {
            float wj = __uint_as_float(__shfl_sync(0xffffffffu, wc.x, j));
            int   cj = __shfl_sync(0xffffffffu, (int)wc.y, j);
            // gather 8 bytes = 4 halves per lane (256B per warp per edge)
            uint2 raw = *((const uint2*)(g_Whh + (size_t)cj * OUT_F) + lane);
            float2 f0 = __half22float2(*(const __half2*)&raw.x);
            float2 f1 = __half22float2(*(const __half2*)&raw.y);
            acc.x = fmaf(wj, f0.x, acc.x);
            acc.y = fmaf(wj, f0.y, acc.y);
            acc.z = fmaf(wj, f1.x, acc.z);
            acc.w = fmaf(wj, f1.y, acc.w);
            sumw += wj;
        }
    }
    float inv = 1.f / (sumw + 1e-10f);
    float4 o;
    o.x = acc.x * inv; o.y = acc.y * inv; o.z = acc.z * inv; o.w = acc.w * inv;
    o.x = o.x > 0.f ? o.x : expf(o.x) - 1.f;
    o.y = o.y > 0.f ? o.y : expf(o.y) - 1.f;
    o.z = o.z > 0.f ? o.z : expf(o.z) - 1.f;
    o.w = o.w > 0.f ? o.w : expf(o.w) - 1.f;
    ((float4*)out)[(size_t)warp * 32 + lane] = o;
}

// ---------------- launch -----------------------------------------------------
extern "C" void kernel_launch(void* const* d_in, const int* in_sizes, int n_in,
                              void* d_out, int out_size) {
    const float* h    = (const float*)d_in[0];
    const int*   rows = (const int*)d_in[1];
    const int*   cols = (const int*)d_in[2];
    const int*   et   = (const int*)d_in[3];
    const float* W    = (const float*)d_in[4];
    const float* rel  = (const float*)d_in[5];
    const float* a    = (const float*)d_in[6];
    float* out = (float*)d_out;

    zero_cnt_kernel<<<(N_NODES + 255) / 256, 256>>>();

    gemm_kernel<<<(N_NODES + 127) / 128, 256>>>(h, W, a, N_NODES);

    rel_dots_kernel<<<(N_REL * 32 + 255) / 256, 256>>>(a, rel);

    count_kernel<<<(N_EDGES + 255) / 256, 256>>>(rows);
    scan_kernel<<<1, 1024>>>();
    scatter_kernel<<<(N_EDGES + 255) / 256, 256>>>(rows, cols, et);

    agg_kernel<<<(N_NODES * 32 + 255) / 256, 256>>>(out);
}